// round 11
// baseline (speedup 1.0000x reference)
#include <cuda_runtime.h>
#include <cstdint>

#define BB 8
#define LL 4096
#define TT 128
#define DH 1024
#define DG 256
#define DP 256

// Scratch (static __device__ — no allocations allowed)
__device__ float g_Q[BB * TT * DP];        // 1 MB
__device__ float g_Qp[BB * TT * DH];       // 4 MB (stored pre-rounded to tf32)
__device__ float g_S[BB * TT * LL];        // 16 MB (alpha stored pre-rounded to tf32)
__device__ float g_P[4][BB * TT * DH];     // 16 MB split-K partials for Z
__device__ int   g_mask_kind;

__device__ __forceinline__ uint32_t f2tf(float f) {
    uint32_t u;
    asm("cvt.rna.tf32.f32 %0, %1;" : "=r"(u) : "f"(f));
    return u;
}
__device__ __forceinline__ uint4 cvt4(float4 v) {
    return make_uint4(f2tf(v.x), f2tf(v.y), f2tf(v.z), f2tf(v.w));
}
__device__ __forceinline__ uint32_t smaddr(const void* p) {
    return (uint32_t)__cvta_generic_to_shared(p);
}
__device__ __forceinline__ void mma8(float* c, const uint32_t* a, const uint32_t* b) {
    asm volatile(
        "mma.sync.aligned.m16n8k8.row.col.f32.tf32.tf32.f32 "
        "{%0,%1,%2,%3}, {%4,%5,%6,%7}, {%8,%9}, {%0,%1,%2,%3};"
        : "+f"(c[0]), "+f"(c[1]), "+f"(c[2]), "+f"(c[3])
        : "r"(a[0]), "r"(a[1]), "r"(a[2]), "r"(a[3]), "r"(b[0]), "r"(b[1]));
}
__device__ __forceinline__ void ldsm4(uint32_t* r, uint32_t addr) {
    asm volatile("ldmatrix.sync.aligned.m8n8.x4.shared.b16 {%0,%1,%2,%3}, [%4];"
                 : "=r"(r[0]), "=r"(r[1]), "=r"(r[2]), "=r"(r[3]) : "r"(addr));
}
__device__ __forceinline__ void cpasync16(uint32_t dst, const void* src) {
    asm volatile("cp.async.ca.shared.global [%0], [%1], 16;" :: "r"(dst), "l"(src));
}
__device__ __forceinline__ void cp_commit() {
    asm volatile("cp.async.commit_group;" ::: "memory");
}
__device__ __forceinline__ void cp_wait0() {
    asm volatile("cp.async.wait_group 0;" ::: "memory");
}
// Plain row pitch (words). Pitch 20 already gives distinct 16B groups for any
// 8 consecutive rows ({0,5,2,7,4,1,6,3} mod 8) -> LDSM conflict-free.
__device__ __forceinline__ int roff(int r) { return r * 20; }

__global__ void detect_mask_kernel(const uint32_t* __restrict__ m) {
    if (threadIdx.x == 0 && blockIdx.x == 0) {
        bool isInt = true, isFloat = true;
        for (int i = 0; i < 256; i++) {
            uint32_t v = m[i];
            if (v != 0u && v != 1u) isInt = false;
            if (v != 0u && v != 0x3f800000u) isFloat = false;
        }
        g_mask_kind = isInt ? 1 : (isFloat ? 2 : 0);
    }
}

// ===== gemm5: BM=128(=M), BN=128, BK=16, 256 threads (8 warps 2x4, warp 64x32) =====
// A [128, K] K-major, values PRE-ROUNDED to tf32 -> staged raw via cp.async.
// COLB=0: B is [N,K] K-major rows (H rows for K3).  COLB=1: B is [K,N] (H for K5),
// transposed into K-major smem at staging. Both use the NT ldmatrix fragment path.
template <bool COLB, int EPI, bool SPLITK>
__global__ __launch_bounds__(256, 2) void gemm5_kernel(
    const float* __restrict__ A, const float* __restrict__ B, float* __restrict__ C,
    int K, int lda, int ldb, int ldc,
    long strideA, long strideB, long strideC, long splitStride,
    const void* __restrict__ maskp, float scale)
{
    const int b = blockIdx.z;
    A += (long)b * strideA;
    B += (long)b * strideB;
    C += (long)b * strideC;
    if (SPLITK) C += (long)blockIdx.y * splitStride;

    __shared__ uint32_t As[2][2560];
    __shared__ uint32_t Bs[2][2560];
    const uint32_t BUFB = 2560 * 4;

    const int tid  = threadIdx.x;
    const int n0   = blockIdx.x * 128;
    const int warp = tid >> 5, lane = tid & 31;
    const int wm = (warp >> 2) * 64, wn = (warp & 3) * 32;
    const int g  = lane >> 2, tg = lane & 3;

    // staging indices: row = tid&127, word-chunk = (tid>>7)*8 (one 32B sector each)
    const int sr = tid & 127;
    const int sc = (tid >> 7) * 8;

    float acc[4][4][4];
    #pragma unroll
    for (int i = 0; i < 4; i++)
        #pragma unroll
        for (int j = 0; j < 4; j++)
            #pragma unroll
            for (int r = 0; r < 4; r++) acc[i][j][r] = 0.f;

    const uint32_t asB = smaddr(&As[0][0]);
    const uint32_t bsB = smaddr(&Bs[0][0]);

    // fragment ldmatrix addresses (buffer 0; add buf*BUFB)
    uint32_t aAd[4], bAd[2];
    #pragma unroll
    for (int mf = 0; mf < 4; mf++) {
        const int row = wm + mf * 16 + (lane & 15);
        aAd[mf] = asB + ((roff(row) + ((lane >> 4) << 2)) << 2);
    }
    #pragma unroll
    for (int p = 0; p < 2; p++) {
        const int row = wn + p * 16 + (lane & 7) + ((lane & 16) >> 1);
        bAd[p] = bsB + ((roff(row) + ((lane & 8) >> 1)) << 2);
    }

    // staging smem dst (words)
    const uint32_t stWord = roff(sr) + sc;
    const uint32_t aDst = asB + (stWord << 2);
    const uint32_t bDst = bsB + (stWord << 2);

    float bV[8];
    auto ldstA = [&](int k0, int buf) {
        const float* ap = A + (long)sr * lda + k0 + sc;
        cpasync16(aDst + buf * BUFB, ap);
        cpasync16(aDst + buf * BUFB + 16, ap + 4);
    };
    auto ldgB = [&](int k0) {
        if (!COLB) {
            const float* bp = B + (long)(n0 + sr) * ldb + k0 + sc;
            float4 v0 = *(const float4*)bp;
            float4 v1 = *(const float4*)(bp + 4);
            bV[0] = v0.x; bV[1] = v0.y; bV[2] = v0.z; bV[3] = v0.w;
            bV[4] = v1.x; bV[5] = v1.y; bV[6] = v1.z; bV[7] = v1.w;
        } else {
            const float* bp = B + (long)(k0 + sc) * ldb + n0 + sr;
            #pragma unroll
            for (int j = 0; j < 8; j++) bV[j] = bp[(long)j * ldb];
        }
    };
    auto stsB = [&](int buf) {
        uint4 u0 = make_uint4(f2tf(bV[0]), f2tf(bV[1]), f2tf(bV[2]), f2tf(bV[3]));
        uint4 u1 = make_uint4(f2tf(bV[4]), f2tf(bV[5]), f2tf(bV[6]), f2tf(bV[7]));
        asm volatile("st.shared.v4.b32 [%0], {%1,%2,%3,%4};"
                     :: "r"(bDst + buf * BUFB), "r"(u0.x), "r"(u0.y), "r"(u0.z), "r"(u0.w));
        asm volatile("st.shared.v4.b32 [%0], {%1,%2,%3,%4};"
                     :: "r"(bDst + buf * BUFB + 16), "r"(u1.x), "r"(u1.y), "r"(u1.z), "r"(u1.w));
    };
    auto compute = [&](int buf) {
        #pragma unroll
        for (int ks = 0; ks < 2; ks++) {
            uint32_t af[4][4];
            #pragma unroll
            for (int mf = 0; mf < 4; mf++)
                ldsm4(af[mf], aAd[mf] + buf * BUFB + ks * 32);
            uint32_t bf[4][2];
            #pragma unroll
            for (int p = 0; p < 2; p++) {
                uint32_t r[4];
                ldsm4(r, bAd[p] + buf * BUFB + ks * 32);
                bf[2 * p][0] = r[0]; bf[2 * p][1] = r[1];
                bf[2 * p + 1][0] = r[2]; bf[2 * p + 1][1] = r[3];
            }
            #pragma unroll
            for (int mf = 0; mf < 4; mf++)
                #pragma unroll
                for (int nf = 0; nf < 4; nf++)
                    mma8(acc[mf][nf], af[mf], bf[nf]);
        }
    };

    const int kBeg  = SPLITK ? blockIdx.y * (K >> 2) : 0;
    const int nIter = (SPLITK ? (K >> 2) : K) >> 4;

    ldgB(kBeg);
    ldstA(kBeg, 0);
    cp_commit();
    stsB(0);
    cp_wait0();
    __syncthreads();
    for (int i = 0; i < nIter; i++) {
        const int buf = i & 1;
        if (i + 1 < nIter) {
            ldgB(kBeg + (i + 1) * 16);
            ldstA(kBeg + (i + 1) * 16, buf ^ 1);
            cp_commit();
        }
        compute(buf);
        if (i + 1 < nIter) stsB(buf ^ 1);
        cp_wait0();
        __syncthreads();
    }

    const float NEG_INF = __int_as_float(0xff800000);
    const int mk = (EPI == 1) ? g_mask_kind : 0;
    #pragma unroll
    for (int mf = 0; mf < 4; mf++) {
        #pragma unroll
        for (int nf = 0; nf < 4; nf++) {
            const int row0 = wm + mf * 16 + g;
            const int col  = n0 + wn + nf * 8 + 2 * tg;
            #pragma unroll
            for (int half = 0; half < 2; half++) {
                const int row = row0 + half * 8;
                float v0 = acc[mf][nf][half * 2 + 0];
                float v1 = acc[mf][nf][half * 2 + 1];
                if (EPI == 1) {
                    v0 *= scale; v1 *= scale;
                    const long mi = (long)b * LL + col;
                    int m0v, m1v;
                    if (mk == 1) {
                        m0v = ((const int*)maskp)[mi];
                        m1v = ((const int*)maskp)[mi + 1];
                    } else if (mk == 2) {
                        m0v = ((const float*)maskp)[mi]     != 0.0f;
                        m1v = ((const float*)maskp)[mi + 1] != 0.0f;
                    } else {
                        m0v = ((const unsigned char*)maskp)[mi];
                        m1v = ((const unsigned char*)maskp)[mi + 1];
                    }
                    if (m0v) v0 = NEG_INF;
                    if (m1v) v1 = NEG_INF;
                }
                *(float2*)&C[(long)row * ldc + col] = make_float2(v0, v1);
            }
        }
    }
}

// ===== gemm3: 128x128 CTA tile (small K1/K2 projections). CVT: store tf32-rounded. =====
template <bool NT, bool CVT>
__global__ __launch_bounds__(256, 2) void gemm3_kernel(
    const float* __restrict__ A, const float* __restrict__ B, float* __restrict__ C,
    int K, int lda, int ldb, int ldc)
{
    __shared__ uint32_t As[2][128 * 20];
    __shared__ uint32_t Bs[2][NT ? 128 * 20 : 16 * 132];

    const int tid  = threadIdx.x;
    const int m0   = blockIdx.y * 128;
    const int n0   = blockIdx.x * 128;
    const int warp = tid >> 5, lane = tid & 31;
    const int wm = (warp >> 2) * 64, wn = (warp & 3) * 32;
    const int g  = lane >> 2, tg = lane & 3;

    const int ar = tid >> 2, acw = (tid & 3) * 4;
    const int br = tid >> 2, bcw = (tid & 3) * 4;
    const int bk = tid >> 4, bnw = (tid & 15) * 4;

    float acc[4][4][4];
    #pragma unroll
    for (int i = 0; i < 4; i++)
        #pragma unroll
        for (int j = 0; j < 4; j++)
            #pragma unroll
            for (int r = 0; r < 4; r++) acc[i][j][r] = 0.f;

    const uint32_t asB = smaddr(&As[0][0]);
    const uint32_t bsB = smaddr(&Bs[0][0]);
    const uint32_t aBase0 = asB + (((wm + (lane & 15)) * 20 + ((lane >> 4) << 2)) << 2);
    const uint32_t bBase0 = bsB + (((wn + (lane & 7) + ((lane & 16) >> 1)) * 20 + ((lane & 8) >> 1)) << 2);
    const uint32_t A_STG = 128 * 20 * 4;
    const uint32_t B_STG = (NT ? 128 * 20 : 16 * 132) * 4;

    float4 aF[2], bF[2];
    auto ldg = [&](int k0) {
        #pragma unroll
        for (int i = 0; i < 2; i++)
            aF[i] = *(const float4*)(A + (long)(m0 + ar + 64 * i) * lda + k0 + acw);
        #pragma unroll
        for (int i = 0; i < 2; i++) {
            if (NT) bF[i] = *(const float4*)(B + (long)(n0 + br + 64 * i) * ldb + k0 + bcw);
            else    bF[i] = *(const float4*)(B + (long)(k0 + bk) * ldb + n0 + bnw + 64 * i);
        }
    };
    auto sts = [&](int buf) {
        #pragma unroll
        for (int i = 0; i < 2; i++)
            *(uint4*)&As[buf][(ar + 64 * i) * 20 + acw] = cvt4(aF[i]);
        #pragma unroll
        for (int i = 0; i < 2; i++) {
            if (NT) *(uint4*)&Bs[buf][(br + 64 * i) * 20 + bcw] = cvt4(bF[i]);
            else    *(uint4*)&Bs[buf][bk * 132 + bnw + 64 * i] = cvt4(bF[i]);
        }
    };
    auto compute = [&](int buf) {
        const uint32_t aB = aBase0 + buf * A_STG;
        const uint32_t bB = bBase0 + buf * B_STG;
        #pragma unroll
        for (int ks = 0; ks < 2; ks++) {
            uint32_t af[4][4];
            #pragma unroll
            for (int mf = 0; mf < 4; mf++)
                ldsm4(af[mf], aB + mf * (16 * 20 * 4) + ks * 32);
            uint32_t bf[4][2];
            if (NT) {
                #pragma unroll
                for (int p = 0; p < 2; p++) {
                    uint32_t r[4];
                    ldsm4(r, bB + p * (16 * 20 * 4) + ks * 32);
                    bf[2 * p][0] = r[0]; bf[2 * p][1] = r[1];
                    bf[2 * p + 1][0] = r[2]; bf[2 * p + 1][1] = r[3];
                }
            } else {
                #pragma unroll
                for (int nf = 0; nf < 4; nf++) {
                    bf[nf][0] = Bs[buf][(ks * 8 + tg) * 132 + wn + nf * 8 + g];
                    bf[nf][1] = Bs[buf][(ks * 8 + tg + 4) * 132 + wn + nf * 8 + g];
                }
            }
            #pragma unroll
            for (int mf = 0; mf < 4; mf++)
                #pragma unroll
                for (int nf = 0; nf < 4; nf++)
                    mma8(acc[mf][nf], af[mf], bf[nf]);
        }
    };

    const int nIter = K >> 4;
    ldg(0);
    sts(0);
    __syncthreads();
    for (int i = 0; i < nIter; i++) {
        if (i + 1 < nIter) ldg((i + 1) * 16);
        compute(i & 1);
        if (i + 1 < nIter) sts((i + 1) & 1);
        __syncthreads();
    }

    #pragma unroll
    for (int mf = 0; mf < 4; mf++) {
        #pragma unroll
        for (int nf = 0; nf < 4; nf++) {
            const int row0 = m0 + wm + mf * 16 + g;
            const int col  = n0 + wn + nf * 8 + 2 * tg;
            #pragma unroll
            for (int half = 0; half < 2; half++) {
                const int row = row0 + half * 8;
                float v0 = acc[mf][nf][half * 2 + 0];
                float v1 = acc[mf][nf][half * 2 + 1];
                if (CVT) { v0 = __uint_as_float(f2tf(v0)); v1 = __uint_as_float(f2tf(v1)); }
                *(float2*)&C[(long)row * ldc + col] = make_float2(v0, v1);
            }
        }
    }
}

// Sum the 4 split-K partials into Z.
__global__ __launch_bounds__(256) void reduce4_kernel(const float4* __restrict__ P, float4* __restrict__ Z) {
    const int idx = blockIdx.x * 256 + threadIdx.x;
    const int n4 = BB * TT * DH / 4;
    float4 a = P[idx], b = P[idx + n4], c = P[idx + 2 * n4], d = P[idx + 3 * n4];
    float4 o;
    o.x = (a.x + b.x) + (c.x + d.x);
    o.y = (a.y + b.y) + (c.y + d.y);
    o.z = (a.z + b.z) + (c.z + d.z);
    o.w = (a.w + b.w) + (c.w + d.w);
    Z[idx] = o;
}

// Single-pass register-resident softmax over L=4096; stores tf32-rounded alpha.
__global__ __launch_bounds__(256) void softmax_kernel(float* __restrict__ S) {
    float4* p = (float4*)(S + (long)blockIdx.x * LL);
    const int tid = threadIdx.x;
    __shared__ float red[8];
    const float NEG_INF = __int_as_float(0xff800000);

    float4 v[4];
    #pragma unroll
    for (int j = 0; j < 4; j++) v[j] = p[tid + 256 * j];

    float m = NEG_INF;
    #pragma unroll
    for (int j = 0; j < 4; j++)
        m = fmaxf(m, fmaxf(fmaxf(v[j].x, v[j].y), fmaxf(v[j].z, v[j].w)));
    #pragma unroll
    for (int o = 16; o; o >>= 1) m = fmaxf(m, __shfl_xor_sync(0xffffffffu, m, o));
    if ((tid & 31) == 0) red[tid >> 5] = m;
    __syncthreads();
    float bm = NEG_INF;
    #pragma unroll
    for (int i = 0; i < 8; i++) bm = fmaxf(bm, red[i]);
    __syncthreads();

    float s = 0.f;
    #pragma unroll
    for (int j = 0; j < 4; j++) {
        v[j].x = __expf(v[j].x - bm); v[j].y = __expf(v[j].y - bm);
        v[j].z = __expf(v[j].z - bm); v[j].w = __expf(v[j].w - bm);
        s += v[j].x + v[j].y + v[j].z + v[j].w;
    }
    #pragma unroll
    for (int o = 16; o; o >>= 1) s += __shfl_xor_sync(0xffffffffu, s, o);
    if ((tid & 31) == 0) red[tid >> 5] = s;
    __syncthreads();
    float bs = 0.f;
    #pragma unroll
    for (int i = 0; i < 8; i++) bs += red[i];
    const float inv = 1.0f / bs;
    #pragma unroll
    for (int j = 0; j < 4; j++) {
        v[j].x = __uint_as_float(f2tf(v[j].x * inv));
        v[j].y = __uint_as_float(f2tf(v[j].y * inv));
        v[j].z = __uint_as_float(f2tf(v[j].z * inv));
        v[j].w = __uint_as_float(f2tf(v[j].w * inv));
        p[tid + 256 * j] = v[j];
    }
}

extern "C" void kernel_launch(void* const* d_in, const int* in_sizes, int n_in,
                              void* d_out, int out_size) {
    const float* H  = (const float*)d_in[0];   // [8,4096,1024]
    const float* G  = (const float*)d_in[1];   // [8,128,256]
    const void*  Mk = d_in[2];                 // [8,4096] bool (dtype detected on device)
    const float* Wk = (const float*)d_in[3];   // [1024,256]
    const float* Wq = (const float*)d_in[4];   // [256,256]
    float* Z = (float*)d_out;                  // [8,128,1024]

    void *pQ, *pQp, *pS, *pP;
    cudaGetSymbolAddress(&pQ,  g_Q);
    cudaGetSymbolAddress(&pQp, g_Qp);
    cudaGetSymbolAddress(&pS,  g_S);
    cudaGetSymbolAddress(&pP,  g_P);
    float* Q  = (float*)pQ;
    float* Qp = (float*)pQp;
    float* S  = (float*)pS;
    float* P  = (float*)pP;

    const float scale = 0.0625f;  // 256^-0.5
    const long ZELEM = (long)BB * TT * DH;

    detect_mask_kernel<<<1, 32>>>((const uint32_t*)Mk);

    // 1) Q = G @ Wq   [1024 x 256] (NN), K=256
    gemm3_kernel<false, false><<<dim3(DP / 128, (BB * TT) / 128, 1), 256>>>(
        G, Wq, Q, DG, DG, DP, DP);

    // 2) Qp = Q @ Wk^T  [1024 x 1024] (NT), K=256, stored tf32-rounded
    gemm3_kernel<true, true><<<dim3(DH / 128, (BB * TT) / 128, 1), 256>>>(
        Q, Wk, Qp, DP, DP, DP, DH);

    // 3) S[b] = scale * Qp[b] @ H[b]^T, masked  [128 x 4096] per batch, K=1024
    gemm5_kernel<false, 1, false><<<dim3(LL / 128, 1, BB), 256>>>(
        Qp, H, S, DH, DH, DH, LL,
        (long)TT * DH, (long)LL * DH, (long)TT * LL, 0, Mk, scale);

    // 4) softmax rows (stores tf32-rounded alpha)
    softmax_kernel<<<BB * TT, 256>>>(S);

    // 5) P[q] = S[b] @ H[b] over K-quarter q  [128 x 1024] per batch, split-K 4
    //    (H transposed at staging -> NT fragment path)
    gemm5_kernel<true, 0, true><<<dim3(DH / 128, 4, BB), 256>>>(
        S, H, P, LL, LL, DH, DH,
        (long)TT * LL, (long)LL * DH, (long)TT * DH, ZELEM, nullptr, 0.f);

    // 6) Z = sum of partials
    reduce4_kernel<<<(int)(ZELEM / 4 / 256), 256>>>((const float4*)P, (float4*)Z);
}

// round 12
// speedup vs baseline: 1.2424x; 1.2424x over previous
#include <cuda_runtime.h>
#include <cstdint>

#define BB 8
#define LL 4096
#define TT 128
#define DH 1024
#define DG 256
#define DP 256

// Scratch (static __device__ — no allocations allowed)
__device__ float g_Q[BB * TT * DP];        // 1 MB
__device__ float g_Qp[BB * TT * DH];       // 4 MB
__device__ float g_S[BB * TT * LL];        // 16 MB
__device__ float g_P[4][BB * TT * DH];     // 16 MB split-K partials for Z
__device__ int   g_mask_kind;

__device__ __forceinline__ uint32_t f2tf(float f) {
    uint32_t u;
    asm("cvt.rna.tf32.f32 %0, %1;" : "=r"(u) : "f"(f));
    return u;
}
__device__ __forceinline__ uint4 cvt4(float4 v) {
    return make_uint4(f2tf(v.x), f2tf(v.y), f2tf(v.z), f2tf(v.w));
}
__device__ __forceinline__ uint32_t smaddr(const void* p) {
    return (uint32_t)__cvta_generic_to_shared(p);
}
__device__ __forceinline__ void mma8(float* c, const uint32_t* a, const uint32_t* b) {
    asm volatile(
        "mma.sync.aligned.m16n8k8.row.col.f32.tf32.tf32.f32 "
        "{%0,%1,%2,%3}, {%4,%5,%6,%7}, {%8,%9}, {%0,%1,%2,%3};"
        : "+f"(c[0]), "+f"(c[1]), "+f"(c[2]), "+f"(c[3])
        : "r"(a[0]), "r"(a[1]), "r"(a[2]), "r"(a[3]), "r"(b[0]), "r"(b[1]));
}
__device__ __forceinline__ void ldsm4(uint32_t* r, uint32_t addr) {
    asm volatile("ldmatrix.sync.aligned.m8n8.x4.shared.b16 {%0,%1,%2,%3}, [%4];"
                 : "=r"(r[0]), "=r"(r[1]), "=r"(r[2]), "=r"(r[3]) : "r"(addr));
}

__global__ void detect_mask_kernel(const uint32_t* __restrict__ m) {
    if (threadIdx.x == 0 && blockIdx.x == 0) {
        bool isInt = true, isFloat = true;
        for (int i = 0; i < 256; i++) {
            uint32_t v = m[i];
            if (v != 0u && v != 1u) isInt = false;
            if (v != 0u && v != 0x3f800000u) isFloat = false;
        }
        g_mask_kind = isInt ? 1 : (isFloat ? 2 : 0);
    }
}

// ===== gemm6: M=128 fixed, BN=128, BK=16; 128 threads (4 warps 2x2, warp 64x64) =====
// R3 pipeline skeleton (ldg->reg, compute, sts, one sync), double-buffered, pitch 20.
// NT: B is [N,K] K-major (ldmatrix B frags).  NN: B is [K,N] (scalar-LDS B frags).
// EPI 1: scale + mask(-inf).  SPLITK: blockIdx.y = K-quarter, C += y*splitStride.
template <bool NT, int EPI, bool SPLITK>
__global__ __launch_bounds__(128, 2) void gemm6_kernel(
    const float* __restrict__ A, const float* __restrict__ B, float* __restrict__ C,
    int K, int lda, int ldb, int ldc,
    long strideA, long strideB, long strideC, long splitStride,
    const void* __restrict__ maskp, float scale)
{
    const int b = blockIdx.z;
    A += (long)b * strideA;
    B += (long)b * strideB;
    C += (long)b * strideC;
    if (SPLITK) C += (long)blockIdx.y * splitStride;

    __shared__ uint32_t As[2][128 * 20];
    __shared__ uint32_t Bs[2][NT ? 128 * 20 : 16 * 132];

    const int tid  = threadIdx.x;
    const int n0   = blockIdx.x * 128;
    const int warp = tid >> 5, lane = tid & 31;
    const int wm = (warp >> 1) * 64, wn = (warp & 1) * 64;
    const int g  = lane >> 2, tg = lane & 3;

    // staging indices
    const int ar = tid >> 2, acw = (tid & 3) * 4;   // A / NT-B: 32 rows per pass, 4 passes
    const int bk = tid >> 4, bnw = (tid & 15) * 8;  // NN-B: 8 rows per pass, 2 passes, 2 f4

    float acc[4][8][4];
    #pragma unroll
    for (int i = 0; i < 4; i++)
        #pragma unroll
        for (int j = 0; j < 8; j++)
            #pragma unroll
            for (int r = 0; r < 4; r++) acc[i][j][r] = 0.f;

    const uint32_t asB = smaddr(&As[0][0]);
    const uint32_t bsB = smaddr(&Bs[0][0]);
    const uint32_t aBase0 = asB + (((wm + (lane & 15)) * 20 + ((lane >> 4) << 2)) << 2);
    const uint32_t bBase0 = bsB + (((wn + (lane & 7) + ((lane & 16) >> 1)) * 20 + ((lane & 8) >> 1)) << 2);
    const uint32_t A_STG = 128 * 20 * 4;
    const uint32_t B_STG = (NT ? 128 * 20 : 16 * 132) * 4;

    float4 aF[4], bF[4];
    auto ldg = [&](int k0) {
        #pragma unroll
        for (int i = 0; i < 4; i++)
            aF[i] = *(const float4*)(A + (long)(ar + 32 * i) * lda + k0 + acw);
        if (NT) {
            #pragma unroll
            for (int i = 0; i < 4; i++)
                bF[i] = *(const float4*)(B + (long)(n0 + ar + 32 * i) * ldb + k0 + acw);
        } else {
            #pragma unroll
            for (int i = 0; i < 2; i++) {
                const float* bp = B + (long)(k0 + bk + 8 * i) * ldb + n0 + bnw;
                bF[2 * i]     = *(const float4*)bp;
                bF[2 * i + 1] = *(const float4*)(bp + 4);
            }
        }
    };
    auto sts = [&](int buf) {
        #pragma unroll
        for (int i = 0; i < 4; i++)
            *(uint4*)&As[buf][(ar + 32 * i) * 20 + acw] = cvt4(aF[i]);
        if (NT) {
            #pragma unroll
            for (int i = 0; i < 4; i++)
                *(uint4*)&Bs[buf][(ar + 32 * i) * 20 + acw] = cvt4(bF[i]);
        } else {
            #pragma unroll
            for (int i = 0; i < 2; i++) {
                *(uint4*)&Bs[buf][(bk + 8 * i) * 132 + bnw]     = cvt4(bF[2 * i]);
                *(uint4*)&Bs[buf][(bk + 8 * i) * 132 + bnw + 4] = cvt4(bF[2 * i + 1]);
            }
        }
    };
    auto compute = [&](int buf) {
        const uint32_t aB = aBase0 + buf * A_STG;
        const uint32_t bB = bBase0 + buf * B_STG;
        #pragma unroll
        for (int ks = 0; ks < 2; ks++) {
            uint32_t af[4][4];
            #pragma unroll
            for (int mf = 0; mf < 4; mf++)
                ldsm4(af[mf], aB + mf * (16 * 20 * 4) + ks * 32);
            uint32_t bf[8][2];
            if (NT) {
                #pragma unroll
                for (int p = 0; p < 4; p++) {
                    uint32_t r[4];
                    ldsm4(r, bB + p * (16 * 20 * 4) + ks * 32);
                    bf[2 * p][0] = r[0]; bf[2 * p][1] = r[1];
                    bf[2 * p + 1][0] = r[2]; bf[2 * p + 1][1] = r[3];
                }
            } else {
                #pragma unroll
                for (int nf = 0; nf < 8; nf++) {
                    bf[nf][0] = Bs[buf][(ks * 8 + tg) * 132 + wn + nf * 8 + g];
                    bf[nf][1] = Bs[buf][(ks * 8 + tg + 4) * 132 + wn + nf * 8 + g];
                }
            }
            #pragma unroll
            for (int mf = 0; mf < 4; mf++)
                #pragma unroll
                for (int nf = 0; nf < 8; nf++)
                    mma8(acc[mf][nf], af[mf], bf[nf]);
        }
    };

    const int kBeg  = SPLITK ? blockIdx.y * (K >> 2) : 0;
    const int nIter = (SPLITK ? (K >> 2) : K) >> 4;

    ldg(kBeg);
    sts(0);
    __syncthreads();
    for (int i = 0; i < nIter; i++) {
        if (i + 1 < nIter) ldg(kBeg + (i + 1) * 16);
        compute(i & 1);
        if (i + 1 < nIter) sts((i + 1) & 1);
        __syncthreads();
    }

    const float NEG_INF = __int_as_float(0xff800000);
    const int mk = (EPI == 1) ? g_mask_kind : 0;
    #pragma unroll
    for (int mf = 0; mf < 4; mf++) {
        #pragma unroll
        for (int nf = 0; nf < 8; nf++) {
            const int row0 = wm + mf * 16 + g;
            const int col  = n0 + wn + nf * 8 + 2 * tg;
            #pragma unroll
            for (int half = 0; half < 2; half++) {
                const int row = row0 + half * 8;
                float v0 = acc[mf][nf][half * 2 + 0];
                float v1 = acc[mf][nf][half * 2 + 1];
                if (EPI == 1) {
                    v0 *= scale; v1 *= scale;
                    const long mi = (long)b * LL + col;
                    int m0v, m1v;
                    if (mk == 1) {
                        m0v = ((const int*)maskp)[mi];
                        m1v = ((const int*)maskp)[mi + 1];
                    } else if (mk == 2) {
                        m0v = ((const float*)maskp)[mi]     != 0.0f;
                        m1v = ((const float*)maskp)[mi + 1] != 0.0f;
                    } else {
                        m0v = ((const unsigned char*)maskp)[mi];
                        m1v = ((const unsigned char*)maskp)[mi + 1];
                    }
                    if (m0v) v0 = NEG_INF;
                    if (m1v) v1 = NEG_INF;
                }
                *(float2*)&C[(long)row * ldc + col] = make_float2(v0, v1);
            }
        }
    }
}

// ===== gemm3: 128x128 CTA tile, 256 threads (small K1/K2 projections) =====
template <bool NT>
__global__ __launch_bounds__(256, 2) void gemm3_kernel(
    const float* __restrict__ A, const float* __restrict__ B, float* __restrict__ C,
    int K, int lda, int ldb, int ldc)
{
    __shared__ uint32_t As[2][128 * 20];
    __shared__ uint32_t Bs[2][NT ? 128 * 20 : 16 * 132];

    const int tid  = threadIdx.x;
    const int m0   = blockIdx.y * 128;
    const int n0   = blockIdx.x * 128;
    const int warp = tid >> 5, lane = tid & 31;
    const int wm = (warp >> 2) * 64, wn = (warp & 3) * 32;
    const int g  = lane >> 2, tg = lane & 3;

    const int ar = tid >> 2, acw = (tid & 3) * 4;
    const int br = tid >> 2, bcw = (tid & 3) * 4;
    const int bk = tid >> 4, bnw = (tid & 15) * 4;

    float acc[4][4][4];
    #pragma unroll
    for (int i = 0; i < 4; i++)
        #pragma unroll
        for (int j = 0; j < 4; j++)
            #pragma unroll
            for (int r = 0; r < 4; r++) acc[i][j][r] = 0.f;

    const uint32_t asB = smaddr(&As[0][0]);
    const uint32_t bsB = smaddr(&Bs[0][0]);
    const uint32_t aBase0 = asB + (((wm + (lane & 15)) * 20 + ((lane >> 4) << 2)) << 2);
    const uint32_t bBase0 = bsB + (((wn + (lane & 7) + ((lane & 16) >> 1)) * 20 + ((lane & 8) >> 1)) << 2);
    const uint32_t A_STG = 128 * 20 * 4;
    const uint32_t B_STG = (NT ? 128 * 20 : 16 * 132) * 4;

    float4 aF[2], bF[2];
    auto ldg = [&](int k0) {
        #pragma unroll
        for (int i = 0; i < 2; i++)
            aF[i] = *(const float4*)(A + (long)(m0 + ar + 64 * i) * lda + k0 + acw);
        #pragma unroll
        for (int i = 0; i < 2; i++) {
            if (NT) bF[i] = *(const float4*)(B + (long)(n0 + br + 64 * i) * ldb + k0 + bcw);
            else    bF[i] = *(const float4*)(B + (long)(k0 + bk) * ldb + n0 + bnw + 64 * i);
        }
    };
    auto sts = [&](int buf) {
        #pragma unroll
        for (int i = 0; i < 2; i++)
            *(uint4*)&As[buf][(ar + 64 * i) * 20 + acw] = cvt4(aF[i]);
        #pragma unroll
        for (int i = 0; i < 2; i++) {
            if (NT) *(uint4*)&Bs[buf][(br + 64 * i) * 20 + bcw] = cvt4(bF[i]);
            else    *(uint4*)&Bs[buf][bk * 132 + bnw + 64 * i] = cvt4(bF[i]);
        }
    };
    auto compute = [&](int buf) {
        const uint32_t aB = aBase0 + buf * A_STG;
        const uint32_t bB = bBase0 + buf * B_STG;
        #pragma unroll
        for (int ks = 0; ks < 2; ks++) {
            uint32_t af[4][4];
            #pragma unroll
            for (int mf = 0; mf < 4; mf++)
                ldsm4(af[mf], aB + mf * (16 * 20 * 4) + ks * 32);
            uint32_t bf[4][2];
            if (NT) {
                #pragma unroll
                for (int p = 0; p < 2; p++) {
                    uint32_t r[4];
                    ldsm4(r, bB + p * (16 * 20 * 4) + ks * 32);
                    bf[2 * p][0] = r[0]; bf[2 * p][1] = r[1];
                    bf[2 * p + 1][0] = r[2]; bf[2 * p + 1][1] = r[3];
                }
            } else {
                #pragma unroll
                for (int nf = 0; nf < 4; nf++) {
                    bf[nf][0] = Bs[buf][(ks * 8 + tg) * 132 + wn + nf * 8 + g];
                    bf[nf][1] = Bs[buf][(ks * 8 + tg + 4) * 132 + wn + nf * 8 + g];
                }
            }
            #pragma unroll
            for (int mf = 0; mf < 4; mf++)
                #pragma unroll
                for (int nf = 0; nf < 4; nf++)
                    mma8(acc[mf][nf], af[mf], bf[nf]);
        }
    };

    const int nIter = K >> 4;
    ldg(0);
    sts(0);
    __syncthreads();
    for (int i = 0; i < nIter; i++) {
        if (i + 1 < nIter) ldg((i + 1) * 16);
        compute(i & 1);
        if (i + 1 < nIter) sts((i + 1) & 1);
        __syncthreads();
    }

    #pragma unroll
    for (int mf = 0; mf < 4; mf++) {
        #pragma unroll
        for (int nf = 0; nf < 4; nf++) {
            const int row0 = m0 + wm + mf * 16 + g;
            const int col  = n0 + wn + nf * 8 + 2 * tg;
            #pragma unroll
            for (int half = 0; half < 2; half++) {
                const int row = row0 + half * 8;
                *(float2*)&C[(long)row * ldc + col] =
                    make_float2(acc[mf][nf][half * 2 + 0], acc[mf][nf][half * 2 + 1]);
            }
        }
    }
}

// Sum the 4 split-K partials into Z.
__global__ __launch_bounds__(256) void reduce4_kernel(const float4* __restrict__ P, float4* __restrict__ Z) {
    const int idx = blockIdx.x * 256 + threadIdx.x;
    const int n4 = BB * TT * DH / 4;
    float4 a = P[idx], b = P[idx + n4], c = P[idx + 2 * n4], d = P[idx + 3 * n4];
    float4 o;
    o.x = (a.x + b.x) + (c.x + d.x);
    o.y = (a.y + b.y) + (c.y + d.y);
    o.z = (a.z + b.z) + (c.z + d.z);
    o.w = (a.w + b.w) + (c.w + d.w);
    Z[idx] = o;
}

// Single-pass register-resident softmax over L=4096. One block of 256 per row.
__global__ __launch_bounds__(256) void softmax_kernel(float* __restrict__ S) {
    float4* p = (float4*)(S + (long)blockIdx.x * LL);
    const int tid = threadIdx.x;
    __shared__ float red[8];
    const float NEG_INF = __int_as_float(0xff800000);

    float4 v[4];
    #pragma unroll
    for (int j = 0; j < 4; j++) v[j] = p[tid + 256 * j];

    float m = NEG_INF;
    #pragma unroll
    for (int j = 0; j < 4; j++)
        m = fmaxf(m, fmaxf(fmaxf(v[j].x, v[j].y), fmaxf(v[j].z, v[j].w)));
    #pragma unroll
    for (int o = 16; o; o >>= 1) m = fmaxf(m, __shfl_xor_sync(0xffffffffu, m, o));
    if ((tid & 31) == 0) red[tid >> 5] = m;
    __syncthreads();
    float bm = NEG_INF;
    #pragma unroll
    for (int i = 0; i < 8; i++) bm = fmaxf(bm, red[i]);
    __syncthreads();

    float s = 0.f;
    #pragma unroll
    for (int j = 0; j < 4; j++) {
        v[j].x = __expf(v[j].x - bm); v[j].y = __expf(v[j].y - bm);
        v[j].z = __expf(v[j].z - bm); v[j].w = __expf(v[j].w - bm);
        s += v[j].x + v[j].y + v[j].z + v[j].w;
    }
    #pragma unroll
    for (int o = 16; o; o >>= 1) s += __shfl_xor_sync(0xffffffffu, s, o);
    if ((tid & 31) == 0) red[tid >> 5] = s;
    __syncthreads();
    float bs = 0.f;
    #pragma unroll
    for (int i = 0; i < 8; i++) bs += red[i];
    const float inv = 1.0f / bs;
    #pragma unroll
    for (int j = 0; j < 4; j++) {
        v[j].x *= inv; v[j].y *= inv; v[j].z *= inv; v[j].w *= inv;
        p[tid + 256 * j] = v[j];
    }
}

extern "C" void kernel_launch(void* const* d_in, const int* in_sizes, int n_in,
                              void* d_out, int out_size) {
    const float* H  = (const float*)d_in[0];   // [8,4096,1024]
    const float* G  = (const float*)d_in[1];   // [8,128,256]
    const void*  Mk = d_in[2];                 // [8,4096] bool (dtype detected on device)
    const float* Wk = (const float*)d_in[3];   // [1024,256]
    const float* Wq = (const float*)d_in[4];   // [256,256]
    float* Z = (float*)d_out;                  // [8,128,1024]

    void *pQ, *pQp, *pS, *pP;
    cudaGetSymbolAddress(&pQ,  g_Q);
    cudaGetSymbolAddress(&pQp, g_Qp);
    cudaGetSymbolAddress(&pS,  g_S);
    cudaGetSymbolAddress(&pP,  g_P);
    float* Q  = (float*)pQ;
    float* Qp = (float*)pQp;
    float* S  = (float*)pS;
    float* P  = (float*)pP;

    const float scale = 0.0625f;  // 256^-0.5
    const long ZELEM = (long)BB * TT * DH;

    detect_mask_kernel<<<1, 32>>>((const uint32_t*)Mk);

    // 1) Q = G @ Wq   [1024 x 256] (NN), K=256
    gemm3_kernel<false><<<dim3(DP / 128, (BB * TT) / 128, 1), 256>>>(
        G, Wq, Q, DG, DG, DP, DP);

    // 2) Qp = Q @ Wk^T  [1024 x 1024] (NT), K=256
    gemm3_kernel<true><<<dim3(DH / 128, (BB * TT) / 128, 1), 256>>>(
        Q, Wk, Qp, DP, DP, DP, DH);

    // 3) S[b] = scale * Qp[b] @ H[b]^T, masked  [128 x 4096] per batch (NT), K=1024
    gemm6_kernel<true, 1, false><<<dim3(LL / 128, 1, BB), 128>>>(
        Qp, H, S, DH, DH, DH, LL,
        (long)TT * DH, (long)LL * DH, (long)TT * LL, 0, Mk, scale);

    // 4) softmax rows
    softmax_kernel<<<BB * TT, 256>>>(S);

    // 5) P[q] = S[b] @ H[b] over K-quarter q  [128 x 1024] per batch (NN), split-K 4
    gemm6_kernel<false, 0, true><<<dim3(DH / 128, 4, BB), 128>>>(
        S, H, P, LL, LL, DH, DH,
        (long)TT * LL, (long)LL * DH, (long)TT * DH, ZELEM, nullptr, 0.f);

    // 6) Z = sum of partials
    reduce4_kernel<<<(int)(ZELEM / 4 / 256), 256>>>((const float4*)P, (float4*)Z);
}

// round 15
// speedup vs baseline: 1.2785x; 1.0291x over previous
#include <cuda_runtime.h>
#include <cstdint>

#define BB 8
#define LL 4096
#define TT 128
#define DH 1024
#define DG 256
#define DP 256

// Scratch (static __device__ — no allocations allowed)
__device__ float g_Q[BB * TT * DP];        // 1 MB
__device__ float g_Qp[BB * TT * DH];       // 4 MB
__device__ float g_S[BB * TT * LL];        // 16 MB
__device__ float g_P[4][BB * TT * DH];     // 16 MB split-K partials for Z
__device__ int   g_mask_kind;

__device__ __forceinline__ uint32_t f2tf(float f) {
    uint32_t u;
    asm("cvt.rna.tf32.f32 %0, %1;" : "=r"(u) : "f"(f));
    return u;
}
__device__ __forceinline__ uint4 cvt4(float4 v) {
    return make_uint4(f2tf(v.x), f2tf(v.y), f2tf(v.z), f2tf(v.w));
}
__device__ __forceinline__ uint32_t smaddr(const void* p) {
    return (uint32_t)__cvta_generic_to_shared(p);
}
__device__ __forceinline__ void mma8(float* c, const uint32_t* a, const uint32_t* b) {
    asm volatile(
        "mma.sync.aligned.m16n8k8.row.col.f32.tf32.tf32.f32 "
        "{%0,%1,%2,%3}, {%4,%5,%6,%7}, {%8,%9}, {%0,%1,%2,%3};"
        : "+f"(c[0]), "+f"(c[1]), "+f"(c[2]), "+f"(c[3])
        : "r"(a[0]), "r"(a[1]), "r"(a[2]), "r"(a[3]), "r"(b[0]), "r"(b[1]));
}
__device__ __forceinline__ void ldsm4(uint32_t* r, uint32_t addr) {
    asm volatile("ldmatrix.sync.aligned.m8n8.x4.shared.b16 {%0,%1,%2,%3}, [%4];"
                 : "=r"(r[0]), "=r"(r[1]), "=r"(r[2]), "=r"(r[3]) : "r"(addr));
}

__global__ void detect_mask_kernel(const uint32_t* __restrict__ m) {
    if (threadIdx.x == 0 && blockIdx.x == 0) {
        bool isInt = true, isFloat = true;
        for (int i = 0; i < 256; i++) {
            uint32_t v = m[i];
            if (v != 0u && v != 1u) isInt = false;
            if (v != 0u && v != 0x3f800000u) isFloat = false;
        }
        g_mask_kind = isInt ? 1 : (isFloat ? 2 : 0);
    }
}

// ===== gemm7: M=128 fixed, BN=128, BK=16; 128 threads (4 warps 2x2, warp 64x64) =====
// R12 pipeline skeleton (ldg->reg, compute, sts, one sync), double-buffered, pitch 20.
// TRB=0: B is [N,K] K-major, staged directly.  TRB=1: B is [K,N] N-contiguous,
// transposed into the SAME K-major smem layout at staging (coalesced column LDG).
// Both use the ldmatrix NT fragment path in compute.
// EPI 1: scale + mask(-inf).  SPLITK: blockIdx.y = K-quarter, C += y*splitStride.
template <bool TRB, int EPI, bool SPLITK>
__global__ __launch_bounds__(128, 2) void gemm7_kernel(
    const float* __restrict__ A, const float* __restrict__ B, float* __restrict__ C,
    int K, int lda, int ldb, int ldc,
    long strideA, long strideB, long strideC, long splitStride,
    const void* __restrict__ maskp, float scale)
{
    const int b = blockIdx.z;
    A += (long)b * strideA;
    B += (long)b * strideB;
    C += (long)b * strideC;
    if (SPLITK) C += (long)blockIdx.y * splitStride;

    __shared__ uint32_t As[2][128 * 20];
    __shared__ uint32_t Bs[2][128 * 20];

    const int tid  = threadIdx.x;
    const int n0   = blockIdx.x * 128;
    const int warp = tid >> 5, lane = tid & 31;
    const int wm = (warp >> 1) * 64, wn = (warp & 1) * 64;
    const int g  = lane >> 2, tg = lane & 3;

    // staging indices (A and direct-B): 32 rows per pass, 4 passes, 1 float4/row
    const int ar = tid >> 2, acw = (tid & 3) * 4;

    float acc[4][8][4];
    #pragma unroll
    for (int i = 0; i < 4; i++)
        #pragma unroll
        for (int j = 0; j < 8; j++)
            #pragma unroll
            for (int r = 0; r < 4; r++) acc[i][j][r] = 0.f;

    const uint32_t asB = smaddr(&As[0][0]);
    const uint32_t bsB = smaddr(&Bs[0][0]);
    const uint32_t aBase0 = asB + (((wm + (lane & 15)) * 20 + ((lane >> 4) << 2)) << 2);
    const uint32_t bBase0 = bsB + (((wn + (lane & 7) + ((lane & 16) >> 1)) * 20 + ((lane & 8) >> 1)) << 2);
    const uint32_t STG = 128 * 20 * 4;

    float4 aF[4], bF[4];
    float  bT[16];
    auto ldg = [&](int k0) {
        #pragma unroll
        for (int i = 0; i < 4; i++)
            aF[i] = *(const float4*)(A + (long)(ar + 32 * i) * lda + k0 + acw);
        if (!TRB) {
            #pragma unroll
            for (int i = 0; i < 4; i++)
                bF[i] = *(const float4*)(B + (long)(n0 + ar + 32 * i) * ldb + k0 + acw);
        } else {
            const float* bp = B + (long)k0 * ldb + n0 + tid;
            #pragma unroll
            for (int j = 0; j < 16; j++) bT[j] = bp[(long)j * ldb];
        }
    };
    auto sts = [&](int buf) {
        #pragma unroll
        for (int i = 0; i < 4; i++)
            *(uint4*)&As[buf][(ar + 32 * i) * 20 + acw] = cvt4(aF[i]);
        if (!TRB) {
            #pragma unroll
            for (int i = 0; i < 4; i++)
                *(uint4*)&Bs[buf][(ar + 32 * i) * 20 + acw] = cvt4(bF[i]);
        } else {
            #pragma unroll
            for (int j = 0; j < 4; j++) {
                uint4 u = make_uint4(f2tf(bT[4 * j]), f2tf(bT[4 * j + 1]),
                                     f2tf(bT[4 * j + 2]), f2tf(bT[4 * j + 3]));
                *(uint4*)&Bs[buf][tid * 20 + 4 * j] = u;
            }
        }
    };
    auto compute = [&](int buf) {
        const uint32_t aB = aBase0 + buf * STG;
        const uint32_t bB = bBase0 + buf * STG;
        #pragma unroll
        for (int ks = 0; ks < 2; ks++) {
            uint32_t af[4][4];
            #pragma unroll
            for (int mf = 0; mf < 4; mf++)
                ldsm4(af[mf], aB + mf * (16 * 20 * 4) + ks * 32);
            uint32_t bf[8][2];
            #pragma unroll
            for (int p = 0; p < 4; p++) {
                uint32_t r[4];
                ldsm4(r, bB + p * (16 * 20 * 4) + ks * 32);
                bf[2 * p][0] = r[0]; bf[2 * p][1] = r[1];
                bf[2 * p + 1][0] = r[2]; bf[2 * p + 1][1] = r[3];
            }
            #pragma unroll
            for (int mf = 0; mf < 4; mf++)
                #pragma unroll
                for (int nf = 0; nf < 8; nf++)
                    mma8(acc[mf][nf], af[mf], bf[nf]);
        }
    };

    const int kBeg  = SPLITK ? blockIdx.y * (K >> 2) : 0;
    const int nIter = (SPLITK ? (K >> 2) : K) >> 4;

    ldg(kBeg);
    sts(0);
    __syncthreads();
    for (int i = 0; i < nIter; i++) {
        if (i + 1 < nIter) ldg(kBeg + (i + 1) * 16);
        compute(i & 1);
        if (i + 1 < nIter) sts((i + 1) & 1);
        __syncthreads();
    }

    const float NEG_INF = __int_as_float(0xff800000);
    const int mk = (EPI == 1) ? g_mask_kind : 0;
    #pragma unroll
    for (int mf = 0; mf < 4; mf++) {
        #pragma unroll
        for (int nf = 0; nf < 8; nf++) {
            const int row0 = wm + mf * 16 + g;
            const int col  = n0 + wn + nf * 8 + 2 * tg;
            #pragma unroll
            for (int half = 0; half < 2; half++) {
                const int row = row0 + half * 8;
                float v0 = acc[mf][nf][half * 2 + 0];
                float v1 = acc[mf][nf][half * 2 + 1];
                if (EPI == 1) {
                    v0 *= scale; v1 *= scale;
                    const long mi = (long)b * LL + col;
                    int m0v, m1v;
                    if (mk == 1) {
                        m0v = ((const int*)maskp)[mi];
                        m1v = ((const int*)maskp)[mi + 1];
                    } else if (mk == 2) {
                        m0v = ((const float*)maskp)[mi]     != 0.0f;
                        m1v = ((const float*)maskp)[mi + 1] != 0.0f;
                    } else {
                        m0v = ((const unsigned char*)maskp)[mi];
                        m1v = ((const unsigned char*)maskp)[mi + 1];
                    }
                    if (m0v) v0 = NEG_INF;
                    if (m1v) v1 = NEG_INF;
                }
                *(float2*)&C[(long)row * ldc + col] = make_float2(v0, v1);
            }
        }
    }
}

// ===== gemm3: 128x128 CTA tile, 256 threads (small K1/K2 projections) =====
template <bool NT>
__global__ __launch_bounds__(256, 2) void gemm3_kernel(
    const float* __restrict__ A, const float* __restrict__ B, float* __restrict__ C,
    int K, int lda, int ldb, int ldc)
{
    __shared__ uint32_t As[2][128 * 20];
    __shared__ uint32_t Bs[2][NT ? 128 * 20 : 16 * 132];

    const int tid  = threadIdx.x;
    const int m0   = blockIdx.y * 128;
    const int n0   = blockIdx.x * 128;
    const int warp = tid >> 5, lane = tid & 31;
    const int wm = (warp >> 2) * 64, wn = (warp & 3) * 32;
    const int g  = lane >> 2, tg = lane & 3;

    const int ar = tid >> 2, acw = (tid & 3) * 4;
    const int br = tid >> 2, bcw = (tid & 3) * 4;
    const int bk = tid >> 4, bnw = (tid & 15) * 4;

    float acc[4][4][4];
    #pragma unroll
    for (int i = 0; i < 4; i++)
        #pragma unroll
        for (int j = 0; j < 4; j++)
            #pragma unroll
            for (int r = 0; r < 4; r++) acc[i][j][r] = 0.f;

    const uint32_t asB = smaddr(&As[0][0]);
    const uint32_t bsB = smaddr(&Bs[0][0]);
    const uint32_t aBase0 = asB + (((wm + (lane & 15)) * 20 + ((lane >> 4) << 2)) << 2);
    const uint32_t bBase0 = bsB + (((wn + (lane & 7) + ((lane & 16) >> 1)) * 20 + ((lane & 8) >> 1)) << 2);
    const uint32_t A_STG = 128 * 20 * 4;
    const uint32_t B_STG = (NT ? 128 * 20 : 16 * 132) * 4;

    float4 aF[2], bF[2];
    auto ldg = [&](int k0) {
        #pragma unroll
        for (int i = 0; i < 2; i++)
            aF[i] = *(const float4*)(A + (long)(m0 + ar + 64 * i) * lda + k0 + acw);
        #pragma unroll
        for (int i = 0; i < 2; i++) {
            if (NT) bF[i] = *(const float4*)(B + (long)(n0 + br + 64 * i) * ldb + k0 + bcw);
            else    bF[i] = *(const float4*)(B + (long)(k0 + bk) * ldb + n0 + bnw + 64 * i);
        }
    };
    auto sts = [&](int buf) {
        #pragma unroll
        for (int i = 0; i < 2; i++)
            *(uint4*)&As[buf][(ar + 64 * i) * 20 + acw] = cvt4(aF[i]);
        #pragma unroll
        for (int i = 0; i < 2; i++) {
            if (NT) *(uint4*)&Bs[buf][(br + 64 * i) * 20 + bcw] = cvt4(bF[i]);
            else    *(uint4*)&Bs[buf][bk * 132 + bnw + 64 * i] = cvt4(bF[i]);
        }
    };
    auto compute = [&](int buf) {
        const uint32_t aB = aBase0 + buf * A_STG;
        const uint32_t bB = bBase0 + buf * B_STG;
        #pragma unroll
        for (int ks = 0; ks < 2; ks++) {
            uint32_t af[4][4];
            #pragma unroll
            for (int mf = 0; mf < 4; mf++)
                ldsm4(af[mf], aB + mf * (16 * 20 * 4) + ks * 32);
            uint32_t bf[4][2];
            if (NT) {
                #pragma unroll
                for (int p = 0; p < 2; p++) {
                    uint32_t r[4];
                    ldsm4(r, bB + p * (16 * 20 * 4) + ks * 32);
                    bf[2 * p][0] = r[0]; bf[2 * p][1] = r[1];
                    bf[2 * p + 1][0] = r[2]; bf[2 * p + 1][1] = r[3];
                }
            } else {
                #pragma unroll
                for (int nf = 0; nf < 4; nf++) {
                    bf[nf][0] = Bs[buf][(ks * 8 + tg) * 132 + wn + nf * 8 + g];
                    bf[nf][1] = Bs[buf][(ks * 8 + tg + 4) * 132 + wn + nf * 8 + g];
                }
            }
            #pragma unroll
            for (int mf = 0; mf < 4; mf++)
                #pragma unroll
                for (int nf = 0; nf < 4; nf++)
                    mma8(acc[mf][nf], af[mf], bf[nf]);
        }
    };

    const int nIter = K >> 4;
    ldg(0);
    sts(0);
    __syncthreads();
    for (int i = 0; i < nIter; i++) {
        if (i + 1 < nIter) ldg((i + 1) * 16);
        compute(i & 1);
        if (i + 1 < nIter) sts((i + 1) & 1);
        __syncthreads();
    }

    #pragma unroll
    for (int mf = 0; mf < 4; mf++) {
        #pragma unroll
        for (int nf = 0; nf < 4; nf++) {
            const int row0 = m0 + wm + mf * 16 + g;
            const int col  = n0 + wn + nf * 8 + 2 * tg;
            #pragma unroll
            for (int half = 0; half < 2; half++) {
                const int row = row0 + half * 8;
                *(float2*)&C[(long)row * ldc + col] =
                    make_float2(acc[mf][nf][half * 2 + 0], acc[mf][nf][half * 2 + 1]);
            }
        }
    }
}

// Sum the 4 split-K partials into Z.
__global__ __launch_bounds__(256) void reduce4_kernel(const float4* __restrict__ P, float4* __restrict__ Z) {
    const int idx = blockIdx.x * 256 + threadIdx.x;
    const int n4 = BB * TT * DH / 4;
    float4 a = P[idx], b = P[idx + n4], c = P[idx + 2 * n4], d = P[idx + 3 * n4];
    float4 o;
    o.x = (a.x + b.x) + (c.x + d.x);
    o.y = (a.y + b.y) + (c.y + d.y);
    o.z = (a.z + b.z) + (c.z + d.z);
    o.w = (a.w + b.w) + (c.w + d.w);
    Z[idx] = o;
}

// Single-pass register-resident softmax over L=4096. One block of 256 per row.
__global__ __launch_bounds__(256) void softmax_kernel(float* __restrict__ S) {
    float4* p = (float4*)(S + (long)blockIdx.x * LL);
    const int tid = threadIdx.x;
    __shared__ float red[8];
    const float NEG_INF = __int_as_float(0xff800000);

    float4 v[4];
    #pragma unroll
    for (int j = 0; j < 4; j++) v[j] = p[tid + 256 * j];

    float m = NEG_INF;
    #pragma unroll
    for (int j = 0; j < 4; j++)
        m = fmaxf(m, fmaxf(fmaxf(v[j].x, v[j].y), fmaxf(v[j].z, v[j].w)));
    #pragma unroll
    for (int o = 16; o; o >>= 1) m = fmaxf(m, __shfl_xor_sync(0xffffffffu, m, o));
    if ((tid & 31) == 0) red[tid >> 5] = m;
    __syncthreads();
    float bm = NEG_INF;
    #pragma unroll
    for (int i = 0; i < 8; i++) bm = fmaxf(bm, red[i]);
    __syncthreads();

    float s = 0.f;
    #pragma unroll
    for (int j = 0; j < 4; j++) {
        v[j].x = __expf(v[j].x - bm); v[j].y = __expf(v[j].y - bm);
        v[j].z = __expf(v[j].z - bm); v[j].w = __expf(v[j].w - bm);
        s += v[j].x + v[j].y + v[j].z + v[j].w;
    }
    #pragma unroll
    for (int o = 16; o; o >>= 1) s += __shfl_xor_sync(0xffffffffu, s, o);
    if ((tid & 31) == 0) red[tid >> 5] = s;
    __syncthreads();
    float bs = 0.f;
    #pragma unroll
    for (int i = 0; i < 8; i++) bs += red[i];
    const float inv = 1.0f / bs;
    #pragma unroll
    for (int j = 0; j < 4; j++) {
        v[j].x *= inv; v[j].y *= inv; v[j].z *= inv; v[j].w *= inv;
        p[tid + 256 * j] = v[j];
    }
}

extern "C" void kernel_launch(void* const* d_in, const int* in_sizes, int n_in,
                              void* d_out, int out_size) {
    const float* H  = (const float*)d_in[0];   // [8,4096,1024]
    const float* G  = (const float*)d_in[1];   // [8,128,256]
    const void*  Mk = d_in[2];                 // [8,4096] bool (dtype detected on device)
    const float* Wk = (const float*)d_in[3];   // [1024,256]
    const float* Wq = (const float*)d_in[4];   // [256,256]
    float* Z = (float*)d_out;                  // [8,128,1024]

    void *pQ, *pQp, *pS, *pP;
    cudaGetSymbolAddress(&pQ,  g_Q);
    cudaGetSymbolAddress(&pQp, g_Qp);
    cudaGetSymbolAddress(&pS,  g_S);
    cudaGetSymbolAddress(&pP,  g_P);
    float* Q  = (float*)pQ;
    float* Qp = (float*)pQp;
    float* S  = (float*)pS;
    float* P  = (float*)pP;

    const float scale = 0.0625f;  // 256^-0.5
    const long ZELEM = (long)BB * TT * DH;

    detect_mask_kernel<<<1, 32>>>((const uint32_t*)Mk);

    // 1) Q = G @ Wq   [1024 x 256] (NN), K=256
    gemm3_kernel<false><<<dim3(DP / 128, (BB * TT) / 128, 1), 256>>>(
        G, Wq, Q, DG, DG, DP, DP);

    // 2) Qp = Q @ Wk^T  [1024 x 1024] (NT), K=256
    gemm3_kernel<true><<<dim3(DH / 128, (BB * TT) / 128, 1), 256>>>(
        Q, Wk, Qp, DP, DP, DP, DH);

    // 3) S[b] = scale * Qp[b] @ H[b]^T, masked  [128 x 4096] per batch (NT direct), K=1024
    gemm7_kernel<false, 1, false><<<dim3(LL / 128, 1, BB), 128>>>(
        Qp, H, S, DH, DH, DH, LL,
        (long)TT * DH, (long)LL * DH, (long)TT * LL, 0, Mk, scale);

    // 4) softmax rows
    softmax_kernel<<<BB * TT, 256>>>(S);

    // 5) P[q] = S[b] @ H[b] over K-quarter q  [128 x 1024] per batch, split-K 4
    //    (H transposed at staging -> ldmatrix NT fragment path)
    gemm7_kernel<true, 0, true><<<dim3(DH / 128, 4, BB), 128>>>(
        S, H, P, LL, LL, DH, DH,
        (long)TT * LL, (long)LL * DH, (long)TT * DH, ZELEM, nullptr, 0.f);

    // 6) Z = sum of partials
    reduce4_kernel<<<(int)(ZELEM / 4 / 256), 256>>>((const float4*)P, (float4*)Z);
}